// round 2
// baseline (speedup 1.0000x reference)
#include <cuda_runtime.h>
#include <math.h>

#define NN    512
#define MEM   1024
#define KD    1024
#define TM3   3072
#define NINT  128
#define IBASE 384

// ---------------- scratch (static device allocation, allowed) ----------------
__device__ float g_XI[NN * TM3];     // x @ ioux_w^T + b   (all nodes)
__device__ float g_XF[NINT * MEM];   // x @ fx_w^T + b     (internal nodes only)
__device__ float g_c [NN * MEM];     // cell states
__device__ float g_hs[NINT * MEM];   // child-sum of h
__device__ float g_t [NINT * MEM];   // W_rel-transformed child-sum
__device__ float g_fc[NINT * MEM];   // sum_k f_k * c_k

__device__ __forceinline__ float sigm(float v) { return 1.0f / (1.0f + expf(-v)); }

// ---------------- SGEMM: C[m,j] = sum_k A[m,k]*B[j,k] + bias[j] --------------
// 64x64 tile, BK=16, 4x4 per thread, simple register prefetch.
// which==0 -> write g_XI, which==1 -> write g_XF (avoids symbol-address host API)
__global__ void __launch_bounds__(256) sgemm_nt(const float* __restrict__ A,
                                                const float* __restrict__ B,
                                                const float* __restrict__ bias,
                                                int Jn, int which)
{
    float* C = which ? g_XF : g_XI;
    __shared__ float As[16][68];
    __shared__ float Bs[16][68];
    int tid = threadIdx.x;
    int tx = tid & 15, ty = tid >> 4;
    int m0 = blockIdx.y * 64, j0 = blockIdx.x * 64;
    int lr = tid >> 2, lc = (tid & 3) * 4;

    const float* Ap = A + (size_t)(m0 + lr) * KD + lc;
    const float* Bp = B + (size_t)(j0 + lr) * KD + lc;
    float4 av = *(const float4*)Ap;
    float4 bv = *(const float4*)Bp;

    float acc[4][4] = {};
    for (int k0 = 0; k0 < KD; k0 += 16) {
        As[lc + 0][lr] = av.x; As[lc + 1][lr] = av.y;
        As[lc + 2][lr] = av.z; As[lc + 3][lr] = av.w;
        Bs[lc + 0][lr] = bv.x; Bs[lc + 1][lr] = bv.y;
        Bs[lc + 2][lr] = bv.z; Bs[lc + 3][lr] = bv.w;
        __syncthreads();
        if (k0 + 16 < KD) {
            av = *(const float4*)(Ap + k0 + 16);
            bv = *(const float4*)(Bp + k0 + 16);
        }
        #pragma unroll
        for (int kk = 0; kk < 16; kk++) {
            float4 a = *(const float4*)&As[kk][ty * 4];
            float4 b = *(const float4*)&Bs[kk][tx * 4];
            acc[0][0] += a.x * b.x; acc[0][1] += a.x * b.y; acc[0][2] += a.x * b.z; acc[0][3] += a.x * b.w;
            acc[1][0] += a.y * b.x; acc[1][1] += a.y * b.y; acc[1][2] += a.y * b.z; acc[1][3] += a.y * b.w;
            acc[2][0] += a.z * b.x; acc[2][1] += a.z * b.y; acc[2][2] += a.z * b.z; acc[2][3] += a.z * b.w;
            acc[3][0] += a.w * b.x; acc[3][1] += a.w * b.y; acc[3][2] += a.w * b.z; acc[3][3] += a.w * b.w;
        }
        __syncthreads();
    }
    #pragma unroll
    for (int i = 0; i < 4; i++) {
        int m = m0 + ty * 4 + i;
        #pragma unroll
        for (int j = 0; j < 4; j++) {
            int jj = j0 + tx * 4 + j;
            C[(size_t)m * Jn + jj] = acc[i][j] + bias[jj];
        }
    }
}

// ---------------- leaves: nodes 0..383, pure elementwise from XI -------------
__global__ void leaf_k(float* __restrict__ h, const float* __restrict__ iouh_b)
{
    int node = blockIdx.y;
    int j = blockIdx.x * 256 + threadIdx.x;
    const float* xi = g_XI + (size_t)node * TM3;
    float ig = sigm(xi[j] + iouh_b[j]);
    float og = sigm(xi[MEM + j] + iouh_b[MEM + j]);
    float ug = tanhf(xi[2 * MEM + j] + iouh_b[2 * MEM + j]);
    float cv = ig * ug;                       // fc == 0 for leaves
    g_c[(size_t)node * MEM + j] = cv;
    h[(size_t)node * MEM + j] = og * tanhf(cv);
}

// ---------------- child-sum of h for one level of internal nodes -------------
__global__ void csum_k(const float* __restrict__ h,
                       const int* __restrict__ child_idx, int n0)
{
    int node = n0 + blockIdx.y;
    int j = blockIdx.x * 256 + threadIdx.x;
    const int* ci = child_idx + node * 4;
    float s = 0.f;
    #pragma unroll
    for (int k = 0; k < 4; k++) {
        int c = ci[k];
        if (c >= 0) s += h[(size_t)c * MEM + j];
    }
    g_hs[(size_t)(node - IBASE) * MEM + j] = s;
}

// ---------------- t = hs @ Wrel[rel]^T (warp per output row) -----------------
__global__ void __launch_bounds__(256) wrel_k(const float* __restrict__ Wrel,
                                              const int* __restrict__ rel_ids, int n0)
{
    int node = n0 + blockIdx.y;
    int li = node - IBASE;
    __shared__ float sh[MEM];
    for (int i = threadIdx.x; i < MEM; i += 256) sh[i] = g_hs[(size_t)li * MEM + i];
    __syncthreads();
    int lane = threadIdx.x & 31;
    int row = blockIdx.x * 8 + (threadIdx.x >> 5);
    const float* W = Wrel + (size_t)rel_ids[node] * (MEM * MEM) + (size_t)row * MEM;
    float s = 0.f;
    #pragma unroll
    for (int it = 0; it < 8; it++) {
        int k4 = (it * 32 + lane) * 4;
        float4 w = *(const float4*)(W + k4);
        float4 x = *(const float4*)(sh + k4);
        s += w.x * x.x + w.y * x.y + w.z * x.z + w.w * x.w;
    }
    #pragma unroll
    for (int o = 16; o; o >>= 1) s += __shfl_xor_sync(0xffffffffu, s, o);
    if (lane == 0) g_t[(size_t)li * MEM + row] = s;
}

// ------------- forget gates + fc = sum_k sigm(fh_w@h_k + b + xf)*c_k ---------
__global__ void __launch_bounds__(256) fh_k(const float* __restrict__ fh_w,
                                            const float* __restrict__ fh_b,
                                            const float* __restrict__ h,
                                            const int* __restrict__ child_idx, int n0)
{
    int node = n0 + blockIdx.y;
    int li = node - IBASE;
    int lane = threadIdx.x & 31;
    int row = blockIdx.x * 8 + (threadIdx.x >> 5);
    int c0 = child_idx[node * 4 + 0], c1 = child_idx[node * 4 + 1];
    int c2 = child_idx[node * 4 + 2], c3 = child_idx[node * 4 + 3];
    const float* W = fh_w + (size_t)row * MEM;
    float s0 = 0.f, s1 = 0.f, s2 = 0.f, s3 = 0.f;
    #pragma unroll
    for (int it = 0; it < 8; it++) {
        int k4 = (it * 32 + lane) * 4;
        float4 w = *(const float4*)(W + k4);
        if (c0 >= 0) { float4 v = *(const float4*)(h + (size_t)c0 * MEM + k4);
                       s0 += w.x * v.x + w.y * v.y + w.z * v.z + w.w * v.w; }
        if (c1 >= 0) { float4 v = *(const float4*)(h + (size_t)c1 * MEM + k4);
                       s1 += w.x * v.x + w.y * v.y + w.z * v.z + w.w * v.w; }
        if (c2 >= 0) { float4 v = *(const float4*)(h + (size_t)c2 * MEM + k4);
                       s2 += w.x * v.x + w.y * v.y + w.z * v.z + w.w * v.w; }
        if (c3 >= 0) { float4 v = *(const float4*)(h + (size_t)c3 * MEM + k4);
                       s3 += w.x * v.x + w.y * v.y + w.z * v.z + w.w * v.w; }
    }
    #pragma unroll
    for (int o = 16; o; o >>= 1) {
        s0 += __shfl_xor_sync(0xffffffffu, s0, o);
        s1 += __shfl_xor_sync(0xffffffffu, s1, o);
        s2 += __shfl_xor_sync(0xffffffffu, s2, o);
        s3 += __shfl_xor_sync(0xffffffffu, s3, o);
    }
    if (lane == 0) {
        float base = fh_b[row] + g_XF[(size_t)li * MEM + row];
        float fc = 0.f;
        if (c0 >= 0) fc += sigm(s0 + base) * g_c[(size_t)c0 * MEM + row];
        if (c1 >= 0) fc += sigm(s1 + base) * g_c[(size_t)c1 * MEM + row];
        if (c2 >= 0) fc += sigm(s2 + base) * g_c[(size_t)c2 * MEM + row];
        if (c3 >= 0) fc += sigm(s3 + base) * g_c[(size_t)c3 * MEM + row];
        g_fc[(size_t)li * MEM + row] = fc;
    }
}

// -------- iou = XI + t @ iouh_w^T + b, fused gate epilogue -> h, c -----------
__global__ void __launch_bounds__(256) iouh_k(const float* __restrict__ iouh_w,
                                              const float* __restrict__ iouh_b,
                                              float* __restrict__ h, int n0)
{
    int node = n0 + blockIdx.y;
    int li = node - IBASE;
    __shared__ float sh[MEM];
    for (int i = threadIdx.x; i < MEM; i += 256) sh[i] = g_t[(size_t)li * MEM + i];
    __syncthreads();
    int lane = threadIdx.x & 31;
    int row = blockIdx.x * 8 + (threadIdx.x >> 5);
    const float* W0 = iouh_w + (size_t)row * MEM;
    const float* W1 = iouh_w + (size_t)(row + MEM) * MEM;
    const float* W2 = iouh_w + (size_t)(row + 2 * MEM) * MEM;
    float s0 = 0.f, s1 = 0.f, s2 = 0.f;
    #pragma unroll
    for (int it = 0; it < 8; it++) {
        int k4 = (it * 32 + lane) * 4;
        float4 x = *(const float4*)(sh + k4);
        float4 w0 = *(const float4*)(W0 + k4);
        s0 += w0.x * x.x + w0.y * x.y + w0.z * x.z + w0.w * x.w;
        float4 w1 = *(const float4*)(W1 + k4);
        s1 += w1.x * x.x + w1.y * x.y + w1.z * x.z + w1.w * x.w;
        float4 w2 = *(const float4*)(W2 + k4);
        s2 += w2.x * x.x + w2.y * x.y + w2.z * x.z + w2.w * x.w;
    }
    #pragma unroll
    for (int o = 16; o; o >>= 1) {
        s0 += __shfl_xor_sync(0xffffffffu, s0, o);
        s1 += __shfl_xor_sync(0xffffffffu, s1, o);
        s2 += __shfl_xor_sync(0xffffffffu, s2, o);
    }
    if (lane == 0) {
        const float* xi = g_XI + (size_t)node * TM3;
        float ig = sigm(s0 + iouh_b[row] + xi[row]);
        float og = sigm(s1 + iouh_b[row + MEM] + xi[MEM + row]);
        float ug = tanhf(s2 + iouh_b[row + 2 * MEM] + xi[2 * MEM + row]);
        float cv = ig * ug + g_fc[(size_t)li * MEM + row];
        g_c[(size_t)node * MEM + row] = cv;
        h[(size_t)node * MEM + row] = og * tanhf(cv);
    }
}

// ------------------------------- launcher ------------------------------------
extern "C" void kernel_launch(void* const* d_in, const int* in_sizes, int n_in,
                              void* d_out, int out_size)
{
    const float* x       = (const float*)d_in[0];
    const float* Wrel    = (const float*)d_in[1];
    const float* ioux_w  = (const float*)d_in[2];
    const float* ioux_b  = (const float*)d_in[3];
    const float* iouh_w  = (const float*)d_in[4];
    const float* iouh_b  = (const float*)d_in[5];
    const float* fx_w    = (const float*)d_in[6];
    const float* fx_b    = (const float*)d_in[7];
    const float* fh_w    = (const float*)d_in[8];
    const float* fh_b    = (const float*)d_in[9];
    const int*   child_idx = (const int*)d_in[10];
    const int*   rel_ids   = (const int*)d_in[11];
    float* h = (float*)d_out;   // h lives directly in the output buffer

    // Hoisted input projections
    sgemm_nt<<<dim3(TM3 / 64, NN / 64), 256>>>(x, ioux_w, ioux_b, TM3, 0);
    sgemm_nt<<<dim3(MEM / 64, NINT / 64), 256>>>(x + (size_t)IBASE * KD,
                                                 fx_w, fx_b, MEM, 1);

    // All 384 leaves in one shot (elementwise only)
    leaf_k<<<dim3(4, 384), 256>>>(h, iouh_b);

    // Internal levels, deepest first (reversed 4-ary heap structure)
    const int lvl_n0[5]  = {384, 427, 491, 507, 511};
    const int lvl_cnt[5] = { 43,  64,  16,   4,   1};
    for (int L = 0; L < 5; L++) {
        int n0 = lvl_n0[L], cnt = lvl_cnt[L];
        csum_k<<<dim3(4, cnt), 256>>>(h, child_idx, n0);
        wrel_k<<<dim3(128, cnt), 256>>>(Wrel, rel_ids, n0);
        fh_k  <<<dim3(128, cnt), 256>>>(fh_w, fh_b, h, child_idx, n0);
        iouh_k<<<dim3(128, cnt), 256>>>(iouh_w, iouh_b, h, n0);
    }
}